// round 1
// baseline (speedup 1.0000x reference)
#include <cuda_runtime.h>

#define B  64
#define C  512
#define S  768
#define K  128
#define KN 256
#define A  200
#define H  1024

#define CSPLIT 8          // c-chunks for x_mean
#define CCHUNK (C / CSPLIT)   // 64
#define KSPLIT 12         // s-chunks for fc GEMM
#define SCHUNK (S / KSPLIT)   // 64

// Scratch (device globals — no allocation allowed)
__device__ float g_xmp[CSPLIT * B * S];   // x-mean partials per c-chunk
__device__ float g_xmean[B * S];          // x_mean
__device__ float g_fcp[KSPLIT * B * H];   // fc partials per s-chunk

// ---------------------------------------------------------------------------
// Kernel 1: partial column means of x.  x: [B, C, S].  Each block handles one
// (b, c-chunk); 192 threads each own one float4 of the S dimension and loop
// over 64 rows of c.  100.7 MB of HBM traffic -> this kernel IS the runtime.
// ---------------------------------------------------------------------------
__global__ void xmean_kernel(const float* __restrict__ x) {
    const int b  = blockIdx.y;
    const int c0 = blockIdx.x * CCHUNK;
    const int s4 = threadIdx.x;                 // 0..191 (S/4)

    const float4* p = reinterpret_cast<const float4*>(x)
                    + ((size_t)b * C + c0) * (S / 4) + s4;

    float sx = 0.f, sy = 0.f, sz = 0.f, sw = 0.f;
#pragma unroll 8
    for (int c = 0; c < CCHUNK; ++c) {
        float4 v = __ldg(p + c * (S / 4));
        sx += v.x; sy += v.y; sz += v.z; sw += v.w;
    }

    float4* dst = reinterpret_cast<float4*>(
        g_xmp + ((size_t)blockIdx.x * B + b) * S) + s4;
    *dst = make_float4(sx, sy, sz, sw);
}

// Reduce the 8 c-chunk partials -> x_mean (deterministic fixed order).
__global__ void xreduce_kernel() {
    const int i = blockIdx.x * 256 + threadIdx.x;   // < B*S = 49152
    float s = 0.f;
#pragma unroll
    for (int c = 0; c < CSPLIT; ++c) s += g_xmp[c * (B * S) + i];
    g_xmean[i] = s * (1.0f / C);
}

// ---------------------------------------------------------------------------
// Kernel 2: fc partials.  fc[b,h] = sum_s x_mean[b,s]*(W_t[h,s] + 4*W_t[h,s+S])
// (local_input = concat(x_mean, 4*x_mean) folded into an effective weight).
// Grid: (16 h-tiles of 64, 12 s-chunks of 64). Block 256 = 16x16 threads,
// 4x4 register tile over [64 b x 64 h].
// ---------------------------------------------------------------------------
__global__ void fc_kernel(const float* __restrict__ W_t) {
    __shared__ float Xs[16][64];      // [sk][b]
    __shared__ float Ws[16][64];      // [sk][h]

    const int h0 = blockIdx.x * 64;
    const int s0 = blockIdx.y * SCHUNK;
    const int tid = threadIdx.x;
    const int tx = tid & 15;          // h group
    const int ty = tid >> 4;          // b group

    float acc[4][4] = {};

    for (int sc = 0; sc < SCHUNK; sc += 16) {
        for (int i = tid; i < 64 * 16; i += 256) {
            int bb = i >> 4, sk = i & 15;
            Xs[sk][bb] = g_xmean[bb * S + s0 + sc + sk];
        }
        for (int i = tid; i < 64 * 16; i += 256) {
            int hh = i >> 4, sk = i & 15;
            int s = s0 + sc + sk;
            const float* wr = W_t + (size_t)(h0 + hh) * (2 * S);
            Ws[sk][hh] = wr[s] + 4.0f * wr[s + S];
        }
        __syncthreads();
#pragma unroll
        for (int sk = 0; sk < 16; ++sk) {
            float a_[4], w_[4];
#pragma unroll
            for (int i = 0; i < 4; ++i) a_[i] = Xs[sk][ty * 4 + i];
#pragma unroll
            for (int j = 0; j < 4; ++j) w_[j] = Ws[sk][tx * 4 + j];
#pragma unroll
            for (int i = 0; i < 4; ++i)
#pragma unroll
                for (int j = 0; j < 4; ++j)
                    acc[i][j] += a_[i] * w_[j];
        }
        __syncthreads();
    }

    float* dst = g_fcp + (size_t)blockIdx.y * (B * H);
#pragma unroll
    for (int i = 0; i < 4; ++i) {
        float4 v = make_float4(acc[i][0], acc[i][1], acc[i][2], acc[i][3]);
        *reinterpret_cast<float4*>(&dst[(ty * 4 + i) * H + h0 + tx * 4]) = v;
    }
}

// ---------------------------------------------------------------------------
// Kernel 3: sum fc partials + bias, BatchNorm over batch (biased var), ReLU.
// One thread per h column (coalesced across h). Writes output #2.
// ---------------------------------------------------------------------------
__global__ void bn_kernel(const float* __restrict__ b_t,
                          const float* __restrict__ gamma,
                          const float* __restrict__ beta,
                          float* __restrict__ out_fc) {
    const int h = blockIdx.x * 256 + threadIdx.x;   // < H
    const float bt_h = b_t[h];

    float v[B];
#pragma unroll
    for (int b = 0; b < B; ++b) v[b] = bt_h;
#pragma unroll
    for (int ks = 0; ks < KSPLIT; ++ks) {
        const float* p = g_fcp + (size_t)ks * (B * H) + h;
#pragma unroll
        for (int b = 0; b < B; ++b) v[b] += p[b * H];
    }

    float mean = 0.f;
#pragma unroll
    for (int b = 0; b < B; ++b) mean += v[b];
    mean *= (1.0f / B);
    float var = 0.f;
#pragma unroll
    for (int b = 0; b < B; ++b) { float d = v[b] - mean; var += d * d; }
    var *= (1.0f / B);

    const float scale = rsqrtf(var + 1e-5f) * gamma[h];
    const float bet = beta[h];
#pragma unroll
    for (int b = 0; b < B; ++b) {
        float r = fmaxf((v[b] - mean) * scale + bet, 0.0f);
        out_fc[b * H + h] = r;
    }
}

// ---------------------------------------------------------------------------
// Kernel 4: per-batch head. score = sigmoid(relu_fc @ W_l^T + b_l) (out #1),
// Q = score @ G_h, omega_next = broadcast(Q) over A (out #3).
// One block per batch row.
// ---------------------------------------------------------------------------
__global__ void head_kernel(const float* __restrict__ W_l,
                            const float* __restrict__ b_l,
                            const float* __restrict__ G_h,
                            const float* __restrict__ relu_in,
                            float* __restrict__ out_score,
                            float* __restrict__ out_omega) {
    __shared__ float r[H];
    __shared__ float sc[K];
    __shared__ float q[KN];
    __shared__ float part[256];

    const int b = blockIdx.x;
    const int tid = threadIdx.x;

    const float* rin = relu_in + (size_t)b * H;
    for (int i = tid; i < H; i += 256) r[i] = rin[i];
    __syncthreads();

    // score: 2 threads per k, each over half of H
    {
        const int k = tid & (K - 1);
        const int half = tid >> 7;
        const float* wl = W_l + (size_t)k * H + half * (H / 2);
        const float* rr = r + half * (H / 2);
        float acc = 0.f;
#pragma unroll 8
        for (int hh = 0; hh < H / 2; ++hh) acc += rr[hh] * wl[hh];
        part[tid] = acc;
        __syncthreads();
        if (tid < K) {
            float z = part[tid] + part[tid + K] + b_l[tid];
            float sv = 1.0f / (1.0f + expf(-z));
            sc[tid] = sv;
            out_score[b * K + tid] = sv;
        }
    }
    __syncthreads();

    // Q[n] = sum_k sc[k] * G_h[k, n]   (coalesced over n)
    {
        float acc = 0.f;
#pragma unroll
        for (int k = 0; k < K; ++k) acc += sc[k] * G_h[k * KN + tid];
        q[tid] = acc;
    }
    __syncthreads();

    // broadcast: out_omega[b, n, a] = Q[n].  A=200 -> 50 float4 per n.
    float4* po = reinterpret_cast<float4*>(out_omega + (size_t)b * KN * A);
    for (int i4 = tid; i4 < KN * A / 4; i4 += 256) {
        float v = q[i4 / (A / 4)];
        po[i4] = make_float4(v, v, v, v);
    }
}

// ---------------------------------------------------------------------------
extern "C" void kernel_launch(void* const* d_in, const int* in_sizes, int n_in,
                              void* d_out, int out_size) {
    const float* x     = (const float*)d_in[0];
    // d_in[1] omega_h, d_in[2] W_s1, d_in[3] W_s2: mathematically dead
    const float* W_t   = (const float*)d_in[4];
    const float* b_t   = (const float*)d_in[5];
    const float* gamma = (const float*)d_in[6];
    const float* beta  = (const float*)d_in[7];
    const float* W_l   = (const float*)d_in[8];
    const float* b_l   = (const float*)d_in[9];
    const float* G_h   = (const float*)d_in[10];

    float* out       = (float*)d_out;
    float* out_score = out;                    // [B, K]
    float* out_fc    = out + B * K;            // [B, H]
    float* out_omega = out + B * K + B * H;    // [B, KN, A]

    xmean_kernel<<<dim3(CSPLIT, B), S / 4>>>(x);
    xreduce_kernel<<<(B * S) / 256, 256>>>();
    fc_kernel<<<dim3(H / 64, KSPLIT), 256>>>(W_t);
    bn_kernel<<<H / 256, 256>>>(b_t, gamma, beta, out_fc);
    head_kernel<<<B, 256>>>(W_l, b_l, G_h, out_fc, out_score, out_omega);
}

// round 2
// speedup vs baseline: 1.6589x; 1.6589x over previous
#include <cuda_runtime.h>

#define B  64
#define C  512
#define S  768
#define K  128
#define KN 256
#define A  200
#define H  1024

#define CSPLIT 8              // c-chunks for x_mean
#define CCHUNK (C / CSPLIT)   // 64
#define KSPLIT 12             // s-chunks for fc GEMM
#define SCHUNK (S / KSPLIT)   // 64

// Scratch (device globals — no allocation allowed)
__device__ float g_xmp[CSPLIT * B * S];   // x-mean partials per c-chunk
__device__ float g_xmean[B * S];          // x_mean
__device__ float g_fcp[KSPLIT * H * B];   // fc partials, layout [ks][h][b]

// ---------------------------------------------------------------------------
// Kernel 1: partial column means of x.  x: [B, C, S].  One block per
// (b, c-chunk); 192 threads each own one float4 of S, loop over 64 c rows.
// 100.7 MB HBM traffic -> this is the unavoidable floor (~13 us).
// ---------------------------------------------------------------------------
__global__ void xmean_kernel(const float* __restrict__ x) {
    const int b  = blockIdx.y;
    const int c0 = blockIdx.x * CCHUNK;
    const int s4 = threadIdx.x;                 // 0..191

    const float4* p = reinterpret_cast<const float4*>(x)
                    + ((size_t)b * C + c0) * (S / 4) + s4;

    float sx = 0.f, sy = 0.f, sz = 0.f, sw = 0.f;
    float tx = 0.f, ty = 0.f, tz = 0.f, tw = 0.f;
#pragma unroll 16
    for (int c = 0; c < CCHUNK; c += 2) {
        float4 v0 = __ldg(p + c * (S / 4));
        float4 v1 = __ldg(p + (c + 1) * (S / 4));
        sx += v0.x; sy += v0.y; sz += v0.z; sw += v0.w;
        tx += v1.x; ty += v1.y; tz += v1.z; tw += v1.w;
    }

    float4* dst = reinterpret_cast<float4*>(
        g_xmp + ((size_t)blockIdx.x * B + b) * S) + s4;
    *dst = make_float4(sx + tx, sy + ty, sz + tz, sw + tw);
}

// Reduce the 8 c-chunk partials -> x_mean (deterministic fixed order).
__global__ void xreduce_kernel() {
    const int i = blockIdx.x * 256 + threadIdx.x;   // < B*S = 49152
    float s = 0.f;
#pragma unroll
    for (int c = 0; c < CSPLIT; ++c) s += g_xmp[c * (B * S) + i];
    g_xmean[i] = s * (1.0f / C);
}

// ---------------------------------------------------------------------------
// Kernel 2: fc partials.  fc[b,h] = sum_s x_mean[b,s]*(W_t[h,s] + 4*W_t[h,s+S])
// (concat(x_mean, 4*x_mean) folded into an effective weight).
// Grid: (16 h-tiles of 64, 12 s-chunks of 64). Block 256 = 16x16 threads,
// 4x4 register tile over [64 h x 64 b]. Output TRANSPOSED: [ks][h][b] so the
// bn reduction reads coalesced with b on lanes.
// ---------------------------------------------------------------------------
__global__ void fc_kernel(const float* __restrict__ W_t) {
    __shared__ float Xs[16][64];      // [sk][b]
    __shared__ float Ws[16][64];      // [sk][h]

    const int h0 = blockIdx.x * 64;
    const int s0 = blockIdx.y * SCHUNK;
    const int tid = threadIdx.x;
    const int tx = tid & 15;          // b group
    const int ty = tid >> 4;          // h group

    float acc[4][4] = {};             // [h][b]

    for (int sc = 0; sc < SCHUNK; sc += 16) {
        for (int i = tid; i < 64 * 16; i += 256) {
            int bb = i >> 4, sk = i & 15;
            Xs[sk][bb] = g_xmean[bb * S + s0 + sc + sk];
        }
        for (int i = tid; i < 64 * 16; i += 256) {
            int hh = i >> 4, sk = i & 15;
            int s = s0 + sc + sk;
            const float* wr = W_t + (size_t)(h0 + hh) * (2 * S);
            Ws[sk][hh] = wr[s] + 4.0f * wr[s + S];
        }
        __syncthreads();
#pragma unroll
        for (int sk = 0; sk < 16; ++sk) {
            float a_[4], w_[4];
#pragma unroll
            for (int i = 0; i < 4; ++i) a_[i] = Ws[sk][ty * 4 + i];
#pragma unroll
            for (int j = 0; j < 4; ++j) w_[j] = Xs[sk][tx * 4 + j];
#pragma unroll
            for (int i = 0; i < 4; ++i)
#pragma unroll
                for (int j = 0; j < 4; ++j)
                    acc[i][j] += a_[i] * w_[j];
        }
        __syncthreads();
    }

    float* dst = g_fcp + (size_t)blockIdx.y * (H * B);
#pragma unroll
    for (int i = 0; i < 4; ++i) {
        float4 v = make_float4(acc[i][0], acc[i][1], acc[i][2], acc[i][3]);
        *reinterpret_cast<float4*>(&dst[(h0 + ty * 4 + i) * B + tx * 4]) = v;
    }
}

// ---------------------------------------------------------------------------
// Kernel 3: sum fc partials + bias, BatchNorm over batch (biased var), ReLU.
// Block = 256 threads = 4 h-columns x 64 b.  Grid = H/4 = 256 blocks.
// All loads coalesced ([ks][h][b] layout). Mean/var via shfl + smem combine.
// ---------------------------------------------------------------------------
__global__ void bn_kernel(const float* __restrict__ b_t,
                          const float* __restrict__ gamma,
                          const float* __restrict__ beta,
                          float* __restrict__ out_fc) {
    const int tid = threadIdx.x;
    const int b   = tid & 63;
    const int hl  = tid >> 6;                  // 0..3
    const int h   = blockIdx.x * 4 + hl;
    const int wh  = (tid >> 5) & 1;            // which half-warp group of b

    __shared__ float ssum[4][2];
    __shared__ float svar[4][2];

    float v = b_t[h];
#pragma unroll
    for (int ks = 0; ks < KSPLIT; ++ks)
        v += g_fcp[(size_t)ks * (H * B) + h * B + b];

    // mean over 64 b (2 warps per h column)
    float s = v;
#pragma unroll
    for (int o = 16; o > 0; o >>= 1) s += __shfl_down_sync(0xffffffffu, s, o);
    if ((tid & 31) == 0) ssum[hl][wh] = s;
    __syncthreads();
    const float mean = (ssum[hl][0] + ssum[hl][1]) * (1.0f / B);

    float d = v - mean;
    float s2 = d * d;
#pragma unroll
    for (int o = 16; o > 0; o >>= 1) s2 += __shfl_down_sync(0xffffffffu, s2, o);
    if ((tid & 31) == 0) svar[hl][wh] = s2;
    __syncthreads();
    const float var = (svar[hl][0] + svar[hl][1]) * (1.0f / B);

    const float r = fmaxf(d * rsqrtf(var + 1e-5f) * gamma[h] + beta[h], 0.0f);
    out_fc[b * H + h] = r;
}

// ---------------------------------------------------------------------------
// Kernel 4: per-batch head. score = sigmoid(relu_fc @ W_l^T + b_l) (out #1),
// Q = score @ G_h, omega_next = broadcast(Q) over A (out #3).
// One block per batch row; warp-per-k with lanes striding H -> coalesced W_l.
// ---------------------------------------------------------------------------
__global__ void head_kernel(const float* __restrict__ W_l,
                            const float* __restrict__ b_l,
                            const float* __restrict__ G_h,
                            const float* __restrict__ relu_in,
                            float* __restrict__ out_score,
                            float* __restrict__ out_omega) {
    __shared__ float r[H];
    __shared__ float sc[K];
    __shared__ float q[KN];

    const int b    = blockIdx.x;
    const int tid  = threadIdx.x;
    const int warp = tid >> 5;
    const int lane = tid & 31;

    const float* rin = relu_in + (size_t)b * H;
    for (int i = tid; i < H; i += 256) r[i] = rin[i];
    __syncthreads();

    // score: each warp owns k = warp, warp+8, ... ; lanes stride over H.
    for (int kk = warp; kk < K; kk += 8) {
        const float* wl = W_l + (size_t)kk * H;
        float acc = 0.f;
#pragma unroll 8
        for (int hh = lane; hh < H; hh += 32) acc += r[hh] * wl[hh];
#pragma unroll
        for (int o = 16; o > 0; o >>= 1)
            acc += __shfl_down_sync(0xffffffffu, acc, o);
        if (lane == 0) {
            float z = acc + b_l[kk];
            float sv = 1.0f / (1.0f + expf(-z));
            sc[kk] = sv;
            out_score[b * K + kk] = sv;
        }
    }
    __syncthreads();

    // Q[n] = sum_k sc[k] * G_h[k, n]   (coalesced over n = tid)
    {
        float acc = 0.f;
#pragma unroll 8
        for (int k = 0; k < K; ++k) acc += sc[k] * G_h[k * KN + tid];
        q[tid] = acc;
    }
    __syncthreads();

    // broadcast: out_omega[b, n, a] = Q[n].  A=200 -> 50 float4 per n.
    float4* po = reinterpret_cast<float4*>(out_omega + (size_t)b * KN * A);
    for (int i4 = tid; i4 < KN * A / 4; i4 += 256) {
        float v = q[i4 / (A / 4)];
        po[i4] = make_float4(v, v, v, v);
    }
}

// ---------------------------------------------------------------------------
extern "C" void kernel_launch(void* const* d_in, const int* in_sizes, int n_in,
                              void* d_out, int out_size) {
    const float* x     = (const float*)d_in[0];
    // d_in[1] omega_h, d_in[2] W_s1, d_in[3] W_s2: mathematically dead
    const float* W_t   = (const float*)d_in[4];
    const float* b_t   = (const float*)d_in[5];
    const float* gamma = (const float*)d_in[6];
    const float* beta  = (const float*)d_in[7];
    const float* W_l   = (const float*)d_in[8];
    const float* b_l   = (const float*)d_in[9];
    const float* G_h   = (const float*)d_in[10];

    float* out       = (float*)d_out;
    float* out_score = out;                    // [B, K]
    float* out_fc    = out + B * K;            // [B, H]
    float* out_omega = out + B * K + B * H;    // [B, KN, A]

    xmean_kernel<<<dim3(CSPLIT, B), S / 4>>>(x);
    xreduce_kernel<<<(B * S) / 256, 256>>>();
    fc_kernel<<<dim3(H / 64, KSPLIT), 256>>>(W_t);
    bn_kernel<<<H / 4, 256>>>(b_t, gamma, beta, out_fc);
    head_kernel<<<B, 256>>>(W_l, b_l, G_h, out_fc, out_score, out_omega);
}

// round 3
// speedup vs baseline: 1.8551x; 1.1183x over previous
#include <cuda_runtime.h>

#define B  64
#define C  512
#define S  768
#define K  128
#define KN 256
#define A  200
#define H  1024

#define CSPLIT 16             // c-chunks for x_mean
#define CCHUNK (C / CSPLIT)   // 32
#define KSPLIT 12             // s-chunks for fc GEMM
#define SCHUNK (S / KSPLIT)   // 64

// Scratch (device globals — no allocation allowed)
__device__ float g_xmp[CSPLIT * B * S];   // x-mean partials per c-chunk
__device__ float g_xmean[B * S];          // x_mean
__device__ float g_fcp[KSPLIT * H * B];   // fc partials, layout [ks][h][b]
__device__ float g_q[B * KN];             // Q = score @ G_h

// ---------------------------------------------------------------------------
// Kernel 1: partial column means of x.  x: [B, C, S].  One block per
// (b, c-chunk of 32); 192 threads each own one float4 of S.  4 independent
// accumulator chains + full unroll -> deep MLP.  100.7 MB HBM = the floor.
// ---------------------------------------------------------------------------
__global__ void xmean_kernel(const float* __restrict__ x) {
    const int b  = blockIdx.y;
    const int c0 = blockIdx.x * CCHUNK;
    const int s4 = threadIdx.x;                 // 0..191

    const float4* p = reinterpret_cast<const float4*>(x)
                    + ((size_t)b * C + c0) * (S / 4) + s4;

    float4 a0 = make_float4(0.f, 0.f, 0.f, 0.f);
    float4 a1 = a0, a2 = a0, a3 = a0;
#pragma unroll
    for (int c = 0; c < CCHUNK; c += 4) {
        float4 v0 = __ldg(p + (c + 0) * (S / 4));
        float4 v1 = __ldg(p + (c + 1) * (S / 4));
        float4 v2 = __ldg(p + (c + 2) * (S / 4));
        float4 v3 = __ldg(p + (c + 3) * (S / 4));
        a0.x += v0.x; a0.y += v0.y; a0.z += v0.z; a0.w += v0.w;
        a1.x += v1.x; a1.y += v1.y; a1.z += v1.z; a1.w += v1.w;
        a2.x += v2.x; a2.y += v2.y; a2.z += v2.z; a2.w += v2.w;
        a3.x += v3.x; a3.y += v3.y; a3.z += v3.z; a3.w += v3.w;
    }

    float4 r = make_float4(a0.x + a1.x + a2.x + a3.x,
                           a0.y + a1.y + a2.y + a3.y,
                           a0.z + a1.z + a2.z + a3.z,
                           a0.w + a1.w + a2.w + a3.w);
    float4* dst = reinterpret_cast<float4*>(
        g_xmp + ((size_t)blockIdx.x * B + b) * S) + s4;
    *dst = r;
}

// Reduce the 16 c-chunk partials -> x_mean (fixed order, float4).
__global__ void xreduce_kernel() {
    const int i = blockIdx.x * 256 + threadIdx.x;     // < B*S/4 = 12288
    const float4* src = reinterpret_cast<const float4*>(g_xmp);
    float4 s = make_float4(0.f, 0.f, 0.f, 0.f);
#pragma unroll
    for (int c = 0; c < CSPLIT; ++c) {
        float4 v = src[c * (B * S / 4) + i];
        s.x += v.x; s.y += v.y; s.z += v.z; s.w += v.w;
    }
    const float inv = 1.0f / C;
    reinterpret_cast<float4*>(g_xmean)[i] =
        make_float4(s.x * inv, s.y * inv, s.z * inv, s.w * inv);
}

// ---------------------------------------------------------------------------
// Kernel 2: fc partials.  fc[b,h] = sum_s x_mean[b,s]*(W_t[h,s] + 4*W_t[h,s+S])
// Grid: (16 h-tiles of 64, 12 s-chunks of 64). Block 256, 4x4 register tile.
// Output layout [ks][h][b] so bn reads coalesced with b on lanes.
// ---------------------------------------------------------------------------
__global__ void fc_kernel(const float* __restrict__ W_t) {
    __shared__ float Xs[16][64];      // [sk][b]
    __shared__ float Ws[16][64];      // [sk][h]

    const int h0 = blockIdx.x * 64;
    const int s0 = blockIdx.y * SCHUNK;
    const int tid = threadIdx.x;
    const int tx = tid & 15;          // b group
    const int ty = tid >> 4;          // h group

    float acc[4][4] = {};             // [h][b]

    for (int sc = 0; sc < SCHUNK; sc += 16) {
        for (int i = tid; i < 64 * 16; i += 256) {
            int bb = i >> 4, sk = i & 15;
            Xs[sk][bb] = g_xmean[bb * S + s0 + sc + sk];
        }
        for (int i = tid; i < 64 * 16; i += 256) {
            int hh = i >> 4, sk = i & 15;
            int s = s0 + sc + sk;
            const float* wr = W_t + (size_t)(h0 + hh) * (2 * S);
            Ws[sk][hh] = wr[s] + 4.0f * wr[s + S];
        }
        __syncthreads();
#pragma unroll
        for (int sk = 0; sk < 16; ++sk) {
            float a_[4], w_[4];
#pragma unroll
            for (int i = 0; i < 4; ++i) a_[i] = Ws[sk][ty * 4 + i];
#pragma unroll
            for (int j = 0; j < 4; ++j) w_[j] = Xs[sk][tx * 4 + j];
#pragma unroll
            for (int i = 0; i < 4; ++i)
#pragma unroll
                for (int j = 0; j < 4; ++j)
                    acc[i][j] += a_[i] * w_[j];
        }
        __syncthreads();
    }

    float* dst = g_fcp + (size_t)blockIdx.y * (H * B);
#pragma unroll
    for (int i = 0; i < 4; ++i) {
        float4 v = make_float4(acc[i][0], acc[i][1], acc[i][2], acc[i][3]);
        *reinterpret_cast<float4*>(&dst[(h0 + ty * 4 + i) * B + tx * 4]) = v;
    }
}

// ---------------------------------------------------------------------------
// Kernel 3: sum fc partials + bias, BatchNorm over batch (biased var), ReLU.
// Block 256 = 16 h-cols x 16 threads; each thread holds 4 b values (float4).
// Grid = H/16 = 64.  12 LDG.128 per thread, width-16 shfl reductions.
// ---------------------------------------------------------------------------
__global__ void bn_kernel(const float* __restrict__ b_t,
                          const float* __restrict__ gamma,
                          const float* __restrict__ beta,
                          float* __restrict__ out_fc) {
    const int tid = threadIdx.x;
    const int bq  = tid & 15;                  // b quad: b = bq*4 .. bq*4+3
    const int hl  = tid >> 4;                  // 0..15
    const int h   = blockIdx.x * 16 + hl;

    const float bt_h = b_t[h];
    float4 v = make_float4(bt_h, bt_h, bt_h, bt_h);
#pragma unroll
    for (int ks = 0; ks < KSPLIT; ++ks) {
        float4 p = *reinterpret_cast<const float4*>(
            g_fcp + (size_t)ks * (H * B) + h * B + bq * 4);
        v.x += p.x; v.y += p.y; v.z += p.z; v.w += p.w;
    }

    // mean over 64 b: 16 lanes x 4 each
    float s = v.x + v.y + v.z + v.w;
#pragma unroll
    for (int o = 8; o > 0; o >>= 1) s += __shfl_down_sync(0xffffffffu, s, o, 16);
    const float mean = __shfl_sync(0xffffffffu, s, 0, 16) * (1.0f / B);

    float4 d = make_float4(v.x - mean, v.y - mean, v.z - mean, v.w - mean);
    float s2 = d.x * d.x + d.y * d.y + d.z * d.z + d.w * d.w;
#pragma unroll
    for (int o = 8; o > 0; o >>= 1) s2 += __shfl_down_sync(0xffffffffu, s2, o, 16);
    const float var = __shfl_sync(0xffffffffu, s2, 0, 16) * (1.0f / B);

    const float scale = rsqrtf(var + 1e-5f) * gamma[h];
    const float bet = beta[h];
    const int b0 = bq * 4;
    out_fc[(b0 + 0) * H + h] = fmaxf(d.x * scale + bet, 0.0f);
    out_fc[(b0 + 1) * H + h] = fmaxf(d.y * scale + bet, 0.0f);
    out_fc[(b0 + 2) * H + h] = fmaxf(d.z * scale + bet, 0.0f);
    out_fc[(b0 + 3) * H + h] = fmaxf(d.w * scale + bet, 0.0f);
}

// ---------------------------------------------------------------------------
// Kernel 4: score = sigmoid(relu_fc @ W_l^T + b_l) (out #1) and Q = score@G_h.
// One block per batch row.  Warp-per-k, float4 loads, 8 LDGs in flight.
// ---------------------------------------------------------------------------
__global__ void score_kernel(const float* __restrict__ W_l,
                             const float* __restrict__ b_l,
                             const float* __restrict__ G_h,
                             const float* __restrict__ relu_in,
                             float* __restrict__ out_score) {
    __shared__ float4 r4[H / 4];     // 256
    __shared__ float sc[K];

    const int b    = blockIdx.x;
    const int tid  = threadIdx.x;
    const int warp = tid >> 5;
    const int lane = tid & 31;

    r4[tid] = reinterpret_cast<const float4*>(relu_in + (size_t)b * H)[tid];
    __syncthreads();

    for (int kk = warp; kk < K; kk += 8) {
        const float4* wl4 = reinterpret_cast<const float4*>(W_l + (size_t)kk * H);
        float acc = 0.f;
#pragma unroll
        for (int j = 0; j < 8; ++j) {
            float4 a = r4[lane + 32 * j];
            float4 w = __ldg(wl4 + lane + 32 * j);
            acc += a.x * w.x + a.y * w.y + a.z * w.z + a.w * w.w;
        }
#pragma unroll
        for (int o = 16; o > 0; o >>= 1)
            acc += __shfl_down_sync(0xffffffffu, acc, o);
        if (lane == 0) {
            float z = acc + b_l[kk];
            float sv = 1.0f / (1.0f + expf(-z));
            sc[kk] = sv;
            out_score[b * K + kk] = sv;
        }
    }
    __syncthreads();

    // Q[n] = sum_k sc[k] * G_h[k, n]   (coalesced over n = tid)
    float acc = 0.f;
#pragma unroll 8
    for (int k = 0; k < K; ++k) acc += sc[k] * G_h[k * KN + tid];
    g_q[b * KN + tid] = acc;
}

// ---------------------------------------------------------------------------
// Kernel 5: omega broadcast (out #3): out_omega[b, n, a] = Q[b, n].
// 13.1 MB streaming write; grid (8 slices, 64 b) = 512 blocks.
// ---------------------------------------------------------------------------
__global__ void bcast_kernel(float* __restrict__ out_omega) {
    const int b  = blockIdx.y;
    const int sl = blockIdx.x;                    // 0..7
    const int tid = threadIdx.x;

    __shared__ float qs[KN / 8];                  // 32 n values
    if (tid < KN / 8) qs[tid] = g_q[b * KN + sl * (KN / 8) + tid];
    __syncthreads();

    // slice covers n in [sl*32, sl*32+32): 32*200 = 6400 floats = 1600 float4
    float4* po = reinterpret_cast<float4*>(
        out_omega + (size_t)b * KN * A + (size_t)sl * (KN / 8) * A);
#pragma unroll
    for (int it = 0; it < 7; ++it) {              // ceil(1600/256)
        int i4 = it * 256 + tid;
        if (i4 < 1600) {
            float v = qs[i4 / (A / 4)];
            po[i4] = make_float4(v, v, v, v);
        }
    }
}

// ---------------------------------------------------------------------------
extern "C" void kernel_launch(void* const* d_in, const int* in_sizes, int n_in,
                              void* d_out, int out_size) {
    const float* x     = (const float*)d_in[0];
    // d_in[1] omega_h, d_in[2] W_s1, d_in[3] W_s2: mathematically dead
    const float* W_t   = (const float*)d_in[4];
    const float* b_t   = (const float*)d_in[5];
    const float* gamma = (const float*)d_in[6];
    const float* beta  = (const float*)d_in[7];
    const float* W_l   = (const float*)d_in[8];
    const float* b_l   = (const float*)d_in[9];
    const float* G_h   = (const float*)d_in[10];

    float* out       = (float*)d_out;
    float* out_score = out;                    // [B, K]
    float* out_fc    = out + B * K;            // [B, H]
    float* out_omega = out + B * K + B * H;    // [B, KN, A]

    xmean_kernel<<<dim3(CSPLIT, B), S / 4>>>(x);
    xreduce_kernel<<<(B * S / 4) / 256, 256>>>();
    fc_kernel<<<dim3(H / 64, KSPLIT), 256>>>(W_t);
    bn_kernel<<<H / 16, 256>>>(b_t, gamma, beta, out_fc);
    score_kernel<<<B, 256>>>(W_l, b_l, G_h, out_fc, out_score);
    bcast_kernel<<<dim3(8, B), 256>>>(out_omega);
}

// round 5
// speedup vs baseline: 2.2651x; 1.2210x over previous
#include <cuda_runtime.h>

#define B  64
#define C  512
#define S  768
#define K  128
#define KN 256
#define A  200
#define H  1024

#define NBLK 256
#define NTHR 256
#define KSPLIT 12

// Scratch (device globals — no allocation allowed)
__device__ float g_xmp[4 * B * S];        // x-mean partials (4 c-quarters)
__device__ float g_xmean[B * S];          // x_mean [b][s]
__device__ float g_fcp[KSPLIT * H * B];   // fc partials [ks][h][b]
__device__ float g_q[B * KN];             // Q = score @ G_h

// Grid-wide sense-reversing barrier state (ints only -> deterministic).
__device__ int          g_bar_count = 0;
__device__ volatile int g_bar_sense = 0;

__device__ __forceinline__ void grid_barrier(int& ls) {
    __syncthreads();
    if (threadIdx.x == 0) {
        const int target = ls ^ 1;
        ls = target;
        __threadfence();
        if (atomicAdd(&g_bar_count, 1) == NBLK - 1) {
            atomicExch(&g_bar_count, 0);
            __threadfence();
            g_bar_sense = target;
        } else {
            while (g_bar_sense != target) { }
        }
        __threadfence();
    } else {
        ls ^= 1;
    }
    __syncthreads();
}

__device__ __forceinline__ void f4add(float4& a, const float4 v) {
    a.x += v.x; a.y += v.y; a.z += v.z; a.w += v.w;
}

__global__ void __launch_bounds__(NTHR, 2)
ham_persistent(const float* __restrict__ x,
               const float* __restrict__ W_t,
               const float* __restrict__ b_t,
               const float* __restrict__ gamma,
               const float* __restrict__ beta,
               const float* __restrict__ W_l,
               const float* __restrict__ b_l,
               const float* __restrict__ G_h,
               float* __restrict__ out_score,
               float* __restrict__ out_fc,
               float* __restrict__ out_omega) {
    __shared__ __align__(16) float sm[4352];   // 17.4 KB, reused per phase

    const int blk = blockIdx.x;
    const int tid = threadIdx.x;
    int ls = g_bar_sense;                      // replay-safe sense init

    // ---------------- Phase 1: x-mean partials -----------------------------
    // block = (cq, b): sum 128 c-rows of x[b] into g_xmp[cq][b][:].
    {
        const int cq = blk >> 6;               // 0..3
        const int b  = blk & 63;
        if (tid < S / 4) {
            const float4* p = reinterpret_cast<const float4*>(x)
                            + ((size_t)b * C + cq * 128) * (S / 4) + tid;
            float4 a0 = make_float4(0.f, 0.f, 0.f, 0.f);
            float4 a1 = a0, a2 = a0, a3 = a0, a4 = a0, a5 = a0, a6 = a0, a7 = a0;
#pragma unroll
            for (int c = 0; c < 128; c += 8) {
                f4add(a0, __ldg(p + (c + 0) * (S / 4)));
                f4add(a1, __ldg(p + (c + 1) * (S / 4)));
                f4add(a2, __ldg(p + (c + 2) * (S / 4)));
                f4add(a3, __ldg(p + (c + 3) * (S / 4)));
                f4add(a4, __ldg(p + (c + 4) * (S / 4)));
                f4add(a5, __ldg(p + (c + 5) * (S / 4)));
                f4add(a6, __ldg(p + (c + 6) * (S / 4)));
                f4add(a7, __ldg(p + (c + 7) * (S / 4)));
            }
            f4add(a0, a1); f4add(a2, a3); f4add(a4, a5); f4add(a6, a7);
            f4add(a0, a2); f4add(a4, a6); f4add(a0, a4);
            reinterpret_cast<float4*>(g_xmp)[(cq * B + b) * (S / 4) + tid] = a0;
        }
    }
    grid_barrier(ls);

    // ---------------- Phase 1b: reduce partials -> x_mean ------------------
    {
        const int g = blk * NTHR + tid;
        if (g < B * S / 4) {
            const float4* src = reinterpret_cast<const float4*>(g_xmp);
            float4 s = src[g];
            f4add(s, src[1 * (B * S / 4) + g]);
            f4add(s, src[2 * (B * S / 4) + g]);
            f4add(s, src[3 * (B * S / 4) + g]);
            const float inv = 1.0f / C;
            reinterpret_cast<float4*>(g_xmean)[g] =
                make_float4(s.x * inv, s.y * inv, s.z * inv, s.w * inv);
        }
    }
    grid_barrier(ls);

    // ---------------- Phase 2: fc partial GEMM -----------------------------
    // fc[b,h] = sum_s x_mean[b,s] * (W_t[h,s] + 4*W_t[h,s+S]).
    // 192 blocks = 16 h-tiles x 12 s-splits; 4x4 register tile; out [ks][h][b].
    if (blk < 16 * KSPLIT) {
        float (*Xs)[64] = reinterpret_cast<float(*)[64]>(sm);          // [sk][b]
        float (*Ws)[64] = reinterpret_cast<float(*)[64]>(sm + 1024);   // [sk][h]
        const int h0 = (blk / KSPLIT) * 64;
        const int s0 = (blk % KSPLIT) * 64;
        const int tx = tid & 15;          // b group
        const int ty = tid >> 4;          // h group

        float acc[4][4] = {};             // [h][b]
        for (int sc = 0; sc < 64; sc += 16) {
            for (int i = tid; i < 1024; i += NTHR) {
                int bb = i >> 4, sk = i & 15;
                Xs[sk][bb] = g_xmean[bb * S + s0 + sc + sk];
            }
            for (int i = tid; i < 1024; i += NTHR) {
                int hh = i >> 4, sk = i & 15;
                int s = s0 + sc + sk;
                const float* wr = W_t + (size_t)(h0 + hh) * (2 * S);
                Ws[sk][hh] = wr[s] + 4.0f * wr[s + S];
            }
            __syncthreads();
#pragma unroll
            for (int sk = 0; sk < 16; ++sk) {
                float a_[4], w_[4];
#pragma unroll
                for (int i = 0; i < 4; ++i) a_[i] = Ws[sk][ty * 4 + i];
#pragma unroll
                for (int j = 0; j < 4; ++j) w_[j] = Xs[sk][tx * 4 + j];
#pragma unroll
                for (int i = 0; i < 4; ++i)
#pragma unroll
                    for (int j = 0; j < 4; ++j)
                        acc[i][j] += a_[i] * w_[j];
            }
            __syncthreads();
        }
        float* dst = g_fcp + (size_t)(blk % KSPLIT) * (H * B);
#pragma unroll
        for (int i = 0; i < 4; ++i) {
            float4 v = make_float4(acc[i][0], acc[i][1], acc[i][2], acc[i][3]);
            *reinterpret_cast<float4*>(&dst[(h0 + ty * 4 + i) * B + tx * 4]) = v;
        }
    }
    grid_barrier(ls);

    // ---------------- Phase 3: BN (biased var over batch) + ReLU -----------
    // block handles 4 h columns x all 64 b; writes out_fc [b][h].
    {
        const int b    = tid & 63;
        const int hl   = tid >> 6;
        const int h    = blk * 4 + hl;
        const int wid  = tid >> 5;
        const int lane = tid & 31;

        float v = b_t[h];
#pragma unroll
        for (int ks = 0; ks < KSPLIT; ++ks)
            v += g_fcp[(size_t)ks * (H * B) + h * B + b];

        float s = v;
#pragma unroll
        for (int o = 16; o; o >>= 1) s += __shfl_down_sync(0xffffffffu, s, o);
        if (!lane) sm[wid] = s;
        __syncthreads();
        const float mean = (sm[hl * 2] + sm[hl * 2 + 1]) * (1.0f / B);

        const float d = v - mean;
        float s2 = d * d;
#pragma unroll
        for (int o = 16; o; o >>= 1) s2 += __shfl_down_sync(0xffffffffu, s2, o);
        if (!lane) sm[8 + wid] = s2;
        __syncthreads();
        const float var = (sm[8 + hl * 2] + sm[8 + hl * 2 + 1]) * (1.0f / B);

        out_fc[b * H + h] =
            fmaxf(d * rsqrtf(var + 1e-5f) * gamma[h] + beta[h], 0.0f);
    }
    grid_barrier(ls);

    // ---------------- Phase 4: score = sigmoid(relu_fc @ W_l^T + b_l) ------
    // block = (b-quad, k-octet): 16 x 16 = 256 blocks. W_l rows reused by 4 b.
    {
        const int b0 = (blk >> 4) * 4;
        const int k0 = (blk & 15) * 8;
        float4* r4 = reinterpret_cast<float4*>(sm);     // [4][256] float4

        for (int i = tid; i < 4 * (H / 4); i += NTHR)
            r4[i] = reinterpret_cast<const float4*>(out_fc)
                        [(b0 + (i >> 8)) * (H / 4) + (i & 255)];
        __syncthreads();

        const int w = tid >> 5, lane = tid & 31;
        const int k = k0 + w;
        const float4* wl4 = reinterpret_cast<const float4*>(W_l + (size_t)k * H);
        float acc0 = 0.f, acc1 = 0.f, acc2 = 0.f, acc3 = 0.f;
#pragma unroll
        for (int j = 0; j < 8; ++j) {
            const float4 wv = __ldg(wl4 + lane + 32 * j);
            const float4 a0 = r4[0 * 256 + lane + 32 * j];
            const float4 a1 = r4[1 * 256 + lane + 32 * j];
            const float4 a2 = r4[2 * 256 + lane + 32 * j];
            const float4 a3 = r4[3 * 256 + lane + 32 * j];
            acc0 += a0.x * wv.x + a0.y * wv.y + a0.z * wv.z + a0.w * wv.w;
            acc1 += a1.x * wv.x + a1.y * wv.y + a1.z * wv.z + a1.w * wv.w;
            acc2 += a2.x * wv.x + a2.y * wv.y + a2.z * wv.z + a2.w * wv.w;
            acc3 += a3.x * wv.x + a3.y * wv.y + a3.z * wv.z + a3.w * wv.w;
        }
#pragma unroll
        for (int o = 16; o; o >>= 1) {
            acc0 += __shfl_down_sync(0xffffffffu, acc0, o);
            acc1 += __shfl_down_sync(0xffffffffu, acc1, o);
            acc2 += __shfl_down_sync(0xffffffffu, acc2, o);
            acc3 += __shfl_down_sync(0xffffffffu, acc3, o);
        }
        if (!lane) {
            const float bl = b_l[k];
            out_score[(b0 + 0) * K + k] = 1.0f / (1.0f + expf(-(acc0 + bl)));
            out_score[(b0 + 1) * K + k] = 1.0f / (1.0f + expf(-(acc1 + bl)));
            out_score[(b0 + 2) * K + k] = 1.0f / (1.0f + expf(-(acc2 + bl)));
            out_score[(b0 + 3) * K + k] = 1.0f / (1.0f + expf(-(acc3 + bl)));
        }
    }
    grid_barrier(ls);

    // ---------------- Phase 4b: Q = score @ G_h ----------------------------
    if (blk < B) {
        if (tid < K) sm[tid] = out_score[blk * K + tid];
        __syncthreads();
        float acc = 0.f;
#pragma unroll 8
        for (int k = 0; k < K; ++k)
            acc += sm[k] * __ldg(G_h + k * KN + tid);
        g_q[blk * KN + tid] = acc;
    }
    grid_barrier(ls);

    // ---------------- Phase 5: omega broadcast -----------------------------
    // out_omega[b, n, a] = Q[b, n]; rows of 50 float4 (A=200).
    // NOTE: plain load of g_q (written by THIS kernel in phase 4b) — __ldg
    // here went through the non-coherent RO path and returned stale data (R4).
    {
        float4* po = reinterpret_cast<float4*>(out_omega);
        const int g = blk * NTHR + tid;
#pragma unroll
        for (int w = 0; w < 13; ++w) {
            const int i4 = g + w * (NBLK * NTHR);
            if (i4 < B * KN * A / 4) {
                const float v = g_q[i4 / (A / 4)];
                po[i4] = make_float4(v, v, v, v);
            }
        }
    }
}

// ---------------------------------------------------------------------------
extern "C" void kernel_launch(void* const* d_in, const int* in_sizes, int n_in,
                              void* d_out, int out_size) {
    const float* x     = (const float*)d_in[0];
    // d_in[1] omega_h, d_in[2] W_s1, d_in[3] W_s2: mathematically dead
    const float* W_t   = (const float*)d_in[4];
    const float* b_t   = (const float*)d_in[5];
    const float* gamma = (const float*)d_in[6];
    const float* beta  = (const float*)d_in[7];
    const float* W_l   = (const float*)d_in[8];
    const float* b_l   = (const float*)d_in[9];
    const float* G_h   = (const float*)d_in[10];

    float* out       = (float*)d_out;
    float* out_score = out;                    // [B, K]
    float* out_fc    = out + B * K;            // [B, H]
    float* out_omega = out + B * K + B * H;    // [B, KN, A]

    ham_persistent<<<NBLK, NTHR>>>(x, W_t, b_t, gamma, beta, W_l, b_l, G_h,
                                   out_score, out_fc, out_omega);
}

// round 6
// speedup vs baseline: 2.8935x; 1.2774x over previous
#include <cuda_runtime.h>

#define B  64
#define C  512
#define S  768
#define K  128
#define KN 256
#define A  200
#define H  1024

#define NBLK 256
#define NTHR 256
#define KSPLIT 16
#define SCHUNK (S / KSPLIT)   // 48

// Scratch (device globals — no allocation allowed)
__device__ float g_xmp[4 * B * S];        // x-sum partials (4 c-quarters) [cq][b][s]
__device__ float g_fcp[KSPLIT * H * B];   // fc partials [ks][h][b]

// Grid-wide sense-reversing barrier state (ints only -> deterministic).
__device__ int          g_bar_count = 0;
__device__ volatile int g_bar_sense = 0;

__device__ __forceinline__ void grid_barrier(int& ls) {
    __syncthreads();
    if (threadIdx.x == 0) {
        const int target = ls ^ 1;
        ls = target;
        __threadfence();
        if (atomicAdd(&g_bar_count, 1) == NBLK - 1) {
            atomicExch(&g_bar_count, 0);
            __threadfence();
            g_bar_sense = target;
        } else {
            while (g_bar_sense != target) { }
        }
        __threadfence();
    } else {
        ls ^= 1;
    }
    __syncthreads();
}

__device__ __forceinline__ void f4add(float4& a, const float4 v) {
    a.x += v.x; a.y += v.y; a.z += v.z; a.w += v.w;
}

__global__ void __launch_bounds__(NTHR, 2)
ham_persistent(const float* __restrict__ x,
               const float* __restrict__ W_t,
               const float* __restrict__ b_t,
               const float* __restrict__ gamma,
               const float* __restrict__ beta,
               const float* __restrict__ W_l,
               const float* __restrict__ b_l,
               const float* __restrict__ G_h,
               float* __restrict__ out_score,
               float* __restrict__ out_fc,
               float* __restrict__ out_omega) {
    __shared__ __align__(16) float sm[4352];   // 17.4 KB, reused per phase

    const int blk = blockIdx.x;
    const int tid = threadIdx.x;
    int ls = g_bar_sense;                      // replay-safe sense init

    // ---------------- Phase 1: x-sum partials ------------------------------
    // block = (cq, b), ALL 256 threads active: cs = c-subgroup (32 rows),
    // s64 = column; each thread accumulates 3 float4 columns over 32 c-rows
    // (12 independent loads in flight), then a smem combine over cs.
    {
        const int cq  = blk >> 6;              // 0..3
        const int b   = blk & 63;
        const int cs  = tid >> 6;              // 0..3
        const int s64 = tid & 63;

        const float4* p = reinterpret_cast<const float4*>(x)
                        + ((size_t)b * C + cq * 128 + cs * 32) * (S / 4);
        float4 a0 = make_float4(0.f, 0.f, 0.f, 0.f);
        float4 a1 = a0, a2 = a0;
#pragma unroll 8
        for (int c = 0; c < 32; ++c) {
            const float4* row = p + c * (S / 4);
            f4add(a0, __ldg(row + s64));
            f4add(a1, __ldg(row + s64 + 64));
            f4add(a2, __ldg(row + s64 + 128));
        }
        float4* sm4 = reinterpret_cast<float4*>(sm);   // [4][192]
        sm4[cs * 192 + s64]       = a0;
        sm4[cs * 192 + s64 + 64]  = a1;
        sm4[cs * 192 + s64 + 128] = a2;
        __syncthreads();
        if (tid < 192) {
            float4 r = sm4[tid];
            f4add(r, sm4[192 + tid]);
            f4add(r, sm4[384 + tid]);
            f4add(r, sm4[576 + tid]);
            reinterpret_cast<float4*>(g_xmp)[(cq * B + b) * (S / 4) + tid] = r;
        }
    }
    grid_barrier(ls);

    // ---------------- Phase 2: fc partial GEMM -----------------------------
    // fc[b,h] = sum_s x_mean[b,s] * (W_t[h,s] + 4*W_t[h,s+S]); x_mean built
    // on the fly from the 4 c-quarter partials (L2-resident, saves a barrier).
    // 256 blocks = 16 h-tiles x 16 s-splits of 48; 4x4 register tile.
    {
        float (*Xs)[64] = reinterpret_cast<float(*)[64]>(sm);          // [sk][b]
        float (*Ws)[64] = reinterpret_cast<float(*)[64]>(sm + 1024);   // [sk][h]
        const int h0 = (blk >> 4) * 64;
        const int s0 = (blk & 15) * SCHUNK;
        const int tx = tid & 15;          // b group
        const int ty = tid >> 4;          // h group

        float acc[4][4] = {};             // [h][b]
        for (int sc = 0; sc < SCHUNK; sc += 16) {
            for (int i = tid; i < 1024; i += NTHR) {
                int bb = i >> 4, sk = i & 15;
                int idx = bb * S + s0 + sc + sk;
                float v = g_xmp[idx] + g_xmp[B * S + idx]
                        + g_xmp[2 * B * S + idx] + g_xmp[3 * B * S + idx];
                Xs[sk][bb] = v * (1.0f / C);
            }
            for (int i = tid; i < 1024; i += NTHR) {
                int hh = i >> 4, sk = i & 15;
                int s = s0 + sc + sk;
                const float* wr = W_t + (size_t)(h0 + hh) * (2 * S);
                Ws[sk][hh] = wr[s] + 4.0f * wr[s + S];
            }
            __syncthreads();
#pragma unroll
            for (int sk = 0; sk < 16; ++sk) {
                float a_[4], w_[4];
#pragma unroll
                for (int i = 0; i < 4; ++i) a_[i] = Ws[sk][ty * 4 + i];
#pragma unroll
                for (int j = 0; j < 4; ++j) w_[j] = Xs[sk][tx * 4 + j];
#pragma unroll
                for (int i = 0; i < 4; ++i)
#pragma unroll
                    for (int j = 0; j < 4; ++j)
                        acc[i][j] += a_[i] * w_[j];
            }
            __syncthreads();
        }
        float* dst = g_fcp + (size_t)(blk & 15) * (H * B);
#pragma unroll
        for (int i = 0; i < 4; ++i) {
            float4 v = make_float4(acc[i][0], acc[i][1], acc[i][2], acc[i][3]);
            *reinterpret_cast<float4*>(&dst[(h0 + ty * 4 + i) * B + tx * 4]) = v;
        }
    }
    grid_barrier(ls);

    // ---------------- Phase 3: BN (biased var over batch) + ReLU -----------
    // block handles 4 h columns x all 64 b; writes out_fc [b][h].
    {
        const int b    = tid & 63;
        const int hl   = tid >> 6;
        const int h    = blk * 4 + hl;
        const int wid  = tid >> 5;
        const int lane = tid & 31;

        float v = b_t[h];
#pragma unroll
        for (int ks = 0; ks < KSPLIT; ++ks)
            v += g_fcp[(size_t)ks * (H * B) + h * B + b];

        float s = v;
#pragma unroll
        for (int o = 16; o; o >>= 1) s += __shfl_down_sync(0xffffffffu, s, o);
        if (!lane) sm[wid] = s;
        __syncthreads();
        const float mean = (sm[hl * 2] + sm[hl * 2 + 1]) * (1.0f / B);

        const float d = v - mean;
        float s2 = d * d;
#pragma unroll
        for (int o = 16; o; o >>= 1) s2 += __shfl_down_sync(0xffffffffu, s2, o);
        if (!lane) sm[8 + wid] = s2;
        __syncthreads();
        const float var = (sm[8 + hl * 2] + sm[8 + hl * 2 + 1]) * (1.0f / B);

        out_fc[b * H + h] =
            fmaxf(d * rsqrtf(var + 1e-5f) * gamma[h] + beta[h], 0.0f);
    }
    grid_barrier(ls);

    // ---------------- Phase 4: score = sigmoid(relu_fc @ W_l^T + b_l) ------
    // block = (b-quad, k-octet): 16 x 16 = 256 blocks. W_l rows reused by 4 b.
    {
        const int b0 = (blk >> 4) * 4;
        const int k0 = (blk & 15) * 8;
        float4* r4 = reinterpret_cast<float4*>(sm);     // [4][256] float4

        for (int i = tid; i < 4 * (H / 4); i += NTHR)
            r4[i] = reinterpret_cast<const float4*>(out_fc)
                        [(b0 + (i >> 8)) * (H / 4) + (i & 255)];
        __syncthreads();

        const int w = tid >> 5, lane = tid & 31;
        const int k = k0 + w;
        const float4* wl4 = reinterpret_cast<const float4*>(W_l + (size_t)k * H);
        float acc0 = 0.f, acc1 = 0.f, acc2 = 0.f, acc3 = 0.f;
#pragma unroll
        for (int j = 0; j < 8; ++j) {
            const float4 wv = __ldg(wl4 + lane + 32 * j);
            const float4 a0 = r4[0 * 256 + lane + 32 * j];
            const float4 a1 = r4[1 * 256 + lane + 32 * j];
            const float4 a2 = r4[2 * 256 + lane + 32 * j];
            const float4 a3 = r4[3 * 256 + lane + 32 * j];
            acc0 += a0.x * wv.x + a0.y * wv.y + a0.z * wv.z + a0.w * wv.w;
            acc1 += a1.x * wv.x + a1.y * wv.y + a1.z * wv.z + a1.w * wv.w;
            acc2 += a2.x * wv.x + a2.y * wv.y + a2.z * wv.z + a2.w * wv.w;
            acc3 += a3.x * wv.x + a3.y * wv.y + a3.z * wv.z + a3.w * wv.w;
        }
#pragma unroll
        for (int o = 16; o; o >>= 1) {
            acc0 += __shfl_down_sync(0xffffffffu, acc0, o);
            acc1 += __shfl_down_sync(0xffffffffu, acc1, o);
            acc2 += __shfl_down_sync(0xffffffffu, acc2, o);
            acc3 += __shfl_down_sync(0xffffffffu, acc3, o);
        }
        if (!lane) {
            const float bl = b_l[k];
            out_score[(b0 + 0) * K + k] = 1.0f / (1.0f + expf(-(acc0 + bl)));
            out_score[(b0 + 1) * K + k] = 1.0f / (1.0f + expf(-(acc1 + bl)));
            out_score[(b0 + 2) * K + k] = 1.0f / (1.0f + expf(-(acc2 + bl)));
            out_score[(b0 + 3) * K + k] = 1.0f / (1.0f + expf(-(acc3 + bl)));
        }
    }
    grid_barrier(ls);

    // ---------------- Phase 5: Q = score @ G_h, omega broadcast ------------
    // block = (b, n-slice of 64): 64 x 4 = 256 blocks. Q computed in smem
    // (4 k-subgroups x 64 n partials), then out_omega[b, n, a] = Q[b, n].
    {
        const int b  = blk >> 2;
        const int n0 = (blk & 3) * 64;
        float* scsh  = sm;          // [128] score
        float* qpart = sm + 128;    // [4][64]
        float* qv    = sm + 384;    // [64]

        if (tid < K) scsh[tid] = out_score[b * K + tid];  // plain load (ours)
        __syncthreads();

        const int kh = tid >> 6;    // 0..3 -> k range [kh*32, kh*32+32)
        const int n  = tid & 63;
        float acc = 0.f;
#pragma unroll 8
        for (int j = 0; j < 32; ++j) {
            const int k = kh * 32 + j;
            acc += scsh[k] * __ldg(G_h + k * KN + n0 + n);
        }
        qpart[kh * 64 + n] = acc;
        __syncthreads();
        if (tid < 64)
            qv[tid] = qpart[tid] + qpart[64 + tid]
                    + qpart[128 + tid] + qpart[192 + tid];
        __syncthreads();

        // write 64 n rows x 200 a = 3200 float4
        float4* po = reinterpret_cast<float4*>(
            out_omega + (size_t)b * KN * A + (size_t)n0 * A);
#pragma unroll
        for (int it = 0; it < 13; ++it) {
            const int i4 = it * NTHR + tid;
            if (i4 < 64 * (A / 4)) {
                const float v = qv[i4 / (A / 4)];
                po[i4] = make_float4(v, v, v, v);
            }
        }
    }
}

// ---------------------------------------------------------------------------
extern "C" void kernel_launch(void* const* d_in, const int* in_sizes, int n_in,
                              void* d_out, int out_size) {
    const float* x     = (const float*)d_in[0];
    // d_in[1] omega_h, d_in[2] W_s1, d_in[3] W_s2: mathematically dead
    const float* W_t   = (const float*)d_in[4];
    const float* b_t   = (const float*)d_in[5];
    const float* gamma = (const float*)d_in[6];
    const float* beta  = (const float*)d_in[7];
    const float* W_l   = (const float*)d_in[8];
    const float* b_l   = (const float*)d_in[9];
    const float* G_h   = (const float*)d_in[10];

    float* out       = (float*)d_out;
    float* out_score = out;                    // [B, K]
    float* out_fc    = out + B * K;            // [B, H]
    float* out_omega = out + B * K + B * H;    // [B, KN, A]

    ham_persistent<<<NBLK, NTHR>>>(x, W_t, b_t, gamma, beta, W_l, b_l, G_h,
                                   out_score, out_fc, out_omega);
}